// round 1
// baseline (speedup 1.0000x reference)
#include <cuda_runtime.h>
#include <math.h>

#define IN_DIM  2976
#define H1_DIM  5952
#define H2_DIM  1488
#define OUT_DIM 744
#define BATCH   8192

#define FEAT_F4 (OUT_DIM / 4)   // 186 float4 per feat row

__device__ __forceinline__ float lrelu(float v) {
    // leaky_relu(0.01): for v>=0, v >= 0.01v; for v<0, 0.01v > v
    return fmaxf(v, 0.01f * v);
}

__device__ __forceinline__ float dot4(float4 a, float4 b) {
    return a.x * b.x + a.y * b.y + a.z * b.z + a.w * b.w;
}

// ---------------------------------------------------------------------------
// Kernel 1: fused block-diagonal sparse MLP -> feat[b, k]
// Each thread owns one k (output feature). Weights (50 floats) live in regs.
// grid = (3, BATCH/B_TILE), block = 256 threads. k = bx*256 + tid.
// ---------------------------------------------------------------------------
template <int B_TILE>
__global__ __launch_bounds__(256)
void sparse_mlp_kernel(const float* __restrict__ x,
                       const float* __restrict__ W1,
                       const float* __restrict__ W2,
                       const float* __restrict__ W3,
                       float* __restrict__ feat)
{
    const int k = blockIdx.x * 256 + threadIdx.x;
    if (k >= OUT_DIM) return;

    // Gather the masked weights for this k directly into registers.
    float4 w1[8];
#pragma unroll
    for (int j = 0; j < 8; j++)
        w1[j] = *(const float4*)(W1 + (size_t)(8 * k + j) * IN_DIM + 4 * k);

    float w20[8], w21[8];
    {
        float4 q;
        q = *(const float4*)(W2 + (size_t)(2 * k + 0) * H1_DIM + 8 * k + 0);
        w20[0] = q.x; w20[1] = q.y; w20[2] = q.z; w20[3] = q.w;
        q = *(const float4*)(W2 + (size_t)(2 * k + 0) * H1_DIM + 8 * k + 4);
        w20[4] = q.x; w20[5] = q.y; w20[6] = q.z; w20[7] = q.w;
        q = *(const float4*)(W2 + (size_t)(2 * k + 1) * H1_DIM + 8 * k + 0);
        w21[0] = q.x; w21[1] = q.y; w21[2] = q.z; w21[3] = q.w;
        q = *(const float4*)(W2 + (size_t)(2 * k + 1) * H1_DIM + 8 * k + 4);
        w21[4] = q.x; w21[5] = q.y; w21[6] = q.z; w21[7] = q.w;
    }
    const float2 w3 = *(const float2*)(W3 + (size_t)k * H2_DIM + 2 * k);

    const int b0 = blockIdx.y * B_TILE;
    const float4* __restrict__ xr = (const float4*)x;  // row stride IN_DIM/4 = 744

#pragma unroll 4
    for (int bi = 0; bi < B_TILE; bi++) {
        const int b = b0 + bi;
        const float4 xv = xr[(size_t)b * (IN_DIM / 4) + k];

        float a0 = 0.f, a1 = 0.f;
#pragma unroll
        for (int j = 0; j < 8; j++) {
            const float v = lrelu(dot4(w1[j], xv));
            a0 += w20[j] * v;
            a1 += w21[j] * v;
        }
        const float f = w3.x * lrelu(a0) + w3.y * lrelu(a1);
        feat[(size_t)b * OUT_DIM + k] = f;
    }
}

// ---------------------------------------------------------------------------
// Kernel 2: heads. warp handles 2 rows. feat fragments in regs (float4),
// 17 dot products (10 reg + 3 c1 + 4 c2), butterfly reduce, softmax.
// ---------------------------------------------------------------------------
__global__ __launch_bounds__(256)
void head_kernel(const float* __restrict__ feat,
                 const float* __restrict__ wo1, const float* __restrict__ bo1,
                 const float* __restrict__ wo2, const float* __restrict__ bo2,
                 const float* __restrict__ wo3, const float* __restrict__ bo3,
                 float* __restrict__ out_reg,
                 float* __restrict__ out_c1,
                 float* __restrict__ out_c2)
{
    const int warp = (blockIdx.x * blockDim.x + threadIdx.x) >> 5;
    const int lane = threadIdx.x & 31;
    const int r0 = warp * 2;
    if (r0 >= BATCH) return;

    const float4* __restrict__ f4 = (const float4*)feat;

    // load feat fragments for both rows (186 float4 per row, 6 iters of 32)
    float4 fa[6], fb[6];
#pragma unroll
    for (int v = 0; v < 6; v++) {
        const int idx = v * 32 + lane;
        const bool ok = idx < FEAT_F4;
        fa[v] = ok ? f4[(size_t)r0 * FEAT_F4 + idx]       : make_float4(0.f, 0.f, 0.f, 0.f);
        fb[v] = ok ? f4[(size_t)(r0 + 1) * FEAT_F4 + idx] : make_float4(0.f, 0.f, 0.f, 0.f);
    }

    float accA[17], accB[17];
#pragma unroll
    for (int o = 0; o < 17; o++) { accA[o] = 0.f; accB[o] = 0.f; }

    // reg head: wo2 rows 0..9 -> slots 0..9
#pragma unroll
    for (int o = 0; o < 10; o++) {
        const float4* wp = (const float4*)(wo2 + (size_t)o * OUT_DIM);
#pragma unroll
        for (int v = 0; v < 6; v++) {
            const int idx = v * 32 + lane;
            if (idx < FEAT_F4) {
                const float4 w = wp[idx];
                accA[o] += dot4(w, fa[v]);
                accB[o] += dot4(w, fb[v]);
            }
        }
    }
    // c1 head: wo1 rows 0..2 -> slots 10..12
#pragma unroll
    for (int o = 0; o < 3; o++) {
        const float4* wp = (const float4*)(wo1 + (size_t)o * OUT_DIM);
#pragma unroll
        for (int v = 0; v < 6; v++) {
            const int idx = v * 32 + lane;
            if (idx < FEAT_F4) {
                const float4 w = wp[idx];
                accA[10 + o] += dot4(w, fa[v]);
                accB[10 + o] += dot4(w, fb[v]);
            }
        }
    }
    // c2 head: wo3 rows 0..3 -> slots 13..16
#pragma unroll
    for (int o = 0; o < 4; o++) {
        const float4* wp = (const float4*)(wo3 + (size_t)o * OUT_DIM);
#pragma unroll
        for (int v = 0; v < 6; v++) {
            const int idx = v * 32 + lane;
            if (idx < FEAT_F4) {
                const float4 w = wp[idx];
                accA[13 + o] += dot4(w, fa[v]);
                accB[13 + o] += dot4(w, fb[v]);
            }
        }
    }

    // butterfly reduce: every lane ends with full sums
#pragma unroll
    for (int o = 0; o < 17; o++) {
#pragma unroll
        for (int s = 16; s > 0; s >>= 1) {
            accA[o] += __shfl_xor_sync(0xffffffffu, accA[o], s);
            accB[o] += __shfl_xor_sync(0xffffffffu, accB[o], s);
        }
    }

    if (lane < 2) {
        const int r = r0 + lane;
        float res[17];
#pragma unroll
        for (int o = 0; o < 17; o++)
            res[o] = (lane == 0) ? accA[o] : accB[o];

        // reg = lrelu(feat @ wo2^T + bo2)
#pragma unroll
        for (int o = 0; o < 10; o++)
            out_reg[(size_t)r * 10 + o] = lrelu(res[o] + bo2[o]);

        // c1 = softmax(lrelu(feat @ wo1^T + bo1)) over 3
        {
            float z0 = lrelu(res[10] + bo1[0]);
            float z1 = lrelu(res[11] + bo1[1]);
            float z2 = lrelu(res[12] + bo1[2]);
            float m = fmaxf(z0, fmaxf(z1, z2));
            float e0 = __expf(z0 - m), e1 = __expf(z1 - m), e2 = __expf(z2 - m);
            float inv = 1.f / (e0 + e1 + e2);
            out_c1[(size_t)r * 3 + 0] = e0 * inv;
            out_c1[(size_t)r * 3 + 1] = e1 * inv;
            out_c1[(size_t)r * 3 + 2] = e2 * inv;
        }
        // c2 = softmax(lrelu(feat @ wo3^T + bo3)) over 4
        {
            float z0 = lrelu(res[13] + bo3[0]);
            float z1 = lrelu(res[14] + bo3[1]);
            float z2 = lrelu(res[15] + bo3[2]);
            float z3 = lrelu(res[16] + bo3[3]);
            float m = fmaxf(fmaxf(z0, z1), fmaxf(z2, z3));
            float e0 = __expf(z0 - m), e1 = __expf(z1 - m);
            float e2 = __expf(z2 - m), e3 = __expf(z3 - m);
            float inv = 1.f / (e0 + e1 + e2 + e3);
            out_c2[(size_t)r * 4 + 0] = e0 * inv;
            out_c2[(size_t)r * 4 + 1] = e1 * inv;
            out_c2[(size_t)r * 4 + 2] = e2 * inv;
            out_c2[(size_t)r * 4 + 3] = e3 * inv;
        }
    }
}

// ---------------------------------------------------------------------------
// launch
// ---------------------------------------------------------------------------
extern "C" void kernel_launch(void* const* d_in, const int* in_sizes, int n_in,
                              void* d_out, int out_size)
{
    // metadata order: x, W1, W2, W3, m1, m2, m3, wo1, bo1, wo2, bo2, wo3, bo3
    const float* x   = (const float*)d_in[0];
    const float* W1  = (const float*)d_in[1];
    const float* W2  = (const float*)d_in[2];
    const float* W3  = (const float*)d_in[3];
    const float* wo1 = (const float*)d_in[7];
    const float* bo1 = (const float*)d_in[8];
    const float* wo2 = (const float*)d_in[9];
    const float* bo2 = (const float*)d_in[10];
    const float* wo3 = (const float*)d_in[11];
    const float* bo3 = (const float*)d_in[12];

    float* out = (float*)d_out;
    // output layout: reg [B,10], c1 [B,3], c2 [B,4], feat [B,744]
    float* out_reg  = out;
    float* out_c1   = out + (size_t)BATCH * 10;
    float* out_c2   = out + (size_t)BATCH * 13;
    float* out_feat = out + (size_t)BATCH * 17;

    constexpr int B_TILE = 64;
    dim3 grid1((OUT_DIM + 255) / 256, BATCH / B_TILE);
    sparse_mlp_kernel<B_TILE><<<grid1, 256>>>(x, W1, W2, W3, out_feat);

    const int warps_needed = BATCH / 2;           // 2 rows per warp
    const int blocks2 = warps_needed / 8;         // 8 warps per block
    head_kernel<<<blocks2, 256>>>(out_feat, wo1, bo1, wo2, bo2, wo3, bo3,
                                  out_reg, out_c1, out_c2);
}

// round 2
// speedup vs baseline: 1.0006x; 1.0006x over previous
#include <cuda_runtime.h>
#include <math.h>

#define IN_DIM  2976
#define H1_DIM  5952
#define H2_DIM  1488
#define OUT_DIM 744
#define BATCH   8192

#define FEAT_F4 (OUT_DIM / 4)   // 186 float4 per feat row

__device__ __forceinline__ float lrelu(float v) {
    // leaky_relu(0.01): for v>=0, v >= 0.01v; for v<0, 0.01v > v
    return fmaxf(v, 0.01f * v);
}

__device__ __forceinline__ float dot4(float4 a, float4 b) {
    return a.x * b.x + a.y * b.y + a.z * b.z + a.w * b.w;
}

// ---------------------------------------------------------------------------
// Kernel 1: fused block-diagonal sparse MLP -> feat[b, k]
// Each thread owns one k (output feature). Weights (50 floats) live in regs.
// grid = (3, BATCH/B_TILE), block = 256 threads. k = bx*256 + tid.
// ---------------------------------------------------------------------------
template <int B_TILE>
__global__ __launch_bounds__(256)
void sparse_mlp_kernel(const float* __restrict__ x,
                       const float* __restrict__ W1,
                       const float* __restrict__ W2,
                       const float* __restrict__ W3,
                       float* __restrict__ feat)
{
    const int k = blockIdx.x * 256 + threadIdx.x;
    if (k >= OUT_DIM) return;

    // Gather the masked weights for this k directly into registers.
    float4 w1[8];
#pragma unroll
    for (int j = 0; j < 8; j++)
        w1[j] = *(const float4*)(W1 + (size_t)(8 * k + j) * IN_DIM + 4 * k);

    float w20[8], w21[8];
    {
        float4 q;
        q = *(const float4*)(W2 + (size_t)(2 * k + 0) * H1_DIM + 8 * k + 0);
        w20[0] = q.x; w20[1] = q.y; w20[2] = q.z; w20[3] = q.w;
        q = *(const float4*)(W2 + (size_t)(2 * k + 0) * H1_DIM + 8 * k + 4);
        w20[4] = q.x; w20[5] = q.y; w20[6] = q.z; w20[7] = q.w;
        q = *(const float4*)(W2 + (size_t)(2 * k + 1) * H1_DIM + 8 * k + 0);
        w21[0] = q.x; w21[1] = q.y; w21[2] = q.z; w21[3] = q.w;
        q = *(const float4*)(W2 + (size_t)(2 * k + 1) * H1_DIM + 8 * k + 4);
        w21[4] = q.x; w21[5] = q.y; w21[6] = q.z; w21[7] = q.w;
    }
    const float2 w3 = *(const float2*)(W3 + (size_t)k * H2_DIM + 2 * k);

    const int b0 = blockIdx.y * B_TILE;
    const float4* __restrict__ xr = (const float4*)x;  // row stride IN_DIM/4 = 744

#pragma unroll 4
    for (int bi = 0; bi < B_TILE; bi++) {
        const int b = b0 + bi;
        const float4 xv = xr[(size_t)b * (IN_DIM / 4) + k];

        float a0 = 0.f, a1 = 0.f;
#pragma unroll
        for (int j = 0; j < 8; j++) {
            const float v = lrelu(dot4(w1[j], xv));
            a0 += w20[j] * v;
            a1 += w21[j] * v;
        }
        const float f = w3.x * lrelu(a0) + w3.y * lrelu(a1);
        feat[(size_t)b * OUT_DIM + k] = f;
    }
}

// ---------------------------------------------------------------------------
// Kernel 2: heads. warp handles 2 rows. feat fragments in regs (float4),
// 17 dot products (10 reg + 3 c1 + 4 c2), butterfly reduce, softmax.
// ---------------------------------------------------------------------------
__global__ __launch_bounds__(256)
void head_kernel(const float* __restrict__ feat,
                 const float* __restrict__ wo1, const float* __restrict__ bo1,
                 const float* __restrict__ wo2, const float* __restrict__ bo2,
                 const float* __restrict__ wo3, const float* __restrict__ bo3,
                 float* __restrict__ out_reg,
                 float* __restrict__ out_c1,
                 float* __restrict__ out_c2)
{
    const int warp = (blockIdx.x * blockDim.x + threadIdx.x) >> 5;
    const int lane = threadIdx.x & 31;
    const int r0 = warp * 2;
    if (r0 >= BATCH) return;

    const float4* __restrict__ f4 = (const float4*)feat;

    // load feat fragments for both rows (186 float4 per row, 6 iters of 32)
    float4 fa[6], fb[6];
#pragma unroll
    for (int v = 0; v < 6; v++) {
        const int idx = v * 32 + lane;
        const bool ok = idx < FEAT_F4;
        fa[v] = ok ? f4[(size_t)r0 * FEAT_F4 + idx]       : make_float4(0.f, 0.f, 0.f, 0.f);
        fb[v] = ok ? f4[(size_t)(r0 + 1) * FEAT_F4 + idx] : make_float4(0.f, 0.f, 0.f, 0.f);
    }

    float accA[17], accB[17];
#pragma unroll
    for (int o = 0; o < 17; o++) { accA[o] = 0.f; accB[o] = 0.f; }

    // reg head: wo2 rows 0..9 -> slots 0..9
#pragma unroll
    for (int o = 0; o < 10; o++) {
        const float4* wp = (const float4*)(wo2 + (size_t)o * OUT_DIM);
#pragma unroll
        for (int v = 0; v < 6; v++) {
            const int idx = v * 32 + lane;
            if (idx < FEAT_F4) {
                const float4 w = wp[idx];
                accA[o] += dot4(w, fa[v]);
                accB[o] += dot4(w, fb[v]);
            }
        }
    }
    // c1 head: wo1 rows 0..2 -> slots 10..12
#pragma unroll
    for (int o = 0; o < 3; o++) {
        const float4* wp = (const float4*)(wo1 + (size_t)o * OUT_DIM);
#pragma unroll
        for (int v = 0; v < 6; v++) {
            const int idx = v * 32 + lane;
            if (idx < FEAT_F4) {
                const float4 w = wp[idx];
                accA[10 + o] += dot4(w, fa[v]);
                accB[10 + o] += dot4(w, fb[v]);
            }
        }
    }
    // c2 head: wo3 rows 0..3 -> slots 13..16
#pragma unroll
    for (int o = 0; o < 4; o++) {
        const float4* wp = (const float4*)(wo3 + (size_t)o * OUT_DIM);
#pragma unroll
        for (int v = 0; v < 6; v++) {
            const int idx = v * 32 + lane;
            if (idx < FEAT_F4) {
                const float4 w = wp[idx];
                accA[13 + o] += dot4(w, fa[v]);
                accB[13 + o] += dot4(w, fb[v]);
            }
        }
    }

    // butterfly reduce: every lane ends with full sums
#pragma unroll
    for (int o = 0; o < 17; o++) {
#pragma unroll
        for (int s = 16; s > 0; s >>= 1) {
            accA[o] += __shfl_xor_sync(0xffffffffu, accA[o], s);
            accB[o] += __shfl_xor_sync(0xffffffffu, accB[o], s);
        }
    }

    if (lane < 2) {
        const int r = r0 + lane;
        float res[17];
#pragma unroll
        for (int o = 0; o < 17; o++)
            res[o] = (lane == 0) ? accA[o] : accB[o];

        // reg = lrelu(feat @ wo2^T + bo2)
#pragma unroll
        for (int o = 0; o < 10; o++)
            out_reg[(size_t)r * 10 + o] = lrelu(res[o] + bo2[o]);

        // c1 = softmax(lrelu(feat @ wo1^T + bo1)) over 3
        {
            float z0 = lrelu(res[10] + bo1[0]);
            float z1 = lrelu(res[11] + bo1[1]);
            float z2 = lrelu(res[12] + bo1[2]);
            float m = fmaxf(z0, fmaxf(z1, z2));
            float e0 = __expf(z0 - m), e1 = __expf(z1 - m), e2 = __expf(z2 - m);
            float inv = 1.f / (e0 + e1 + e2);
            out_c1[(size_t)r * 3 + 0] = e0 * inv;
            out_c1[(size_t)r * 3 + 1] = e1 * inv;
            out_c1[(size_t)r * 3 + 2] = e2 * inv;
        }
        // c2 = softmax(lrelu(feat @ wo3^T + bo3)) over 4
        {
            float z0 = lrelu(res[13] + bo3[0]);
            float z1 = lrelu(res[14] + bo3[1]);
            float z2 = lrelu(res[15] + bo3[2]);
            float z3 = lrelu(res[16] + bo3[3]);
            float m = fmaxf(fmaxf(z0, z1), fmaxf(z2, z3));
            float e0 = __expf(z0 - m), e1 = __expf(z1 - m);
            float e2 = __expf(z2 - m), e3 = __expf(z3 - m);
            float inv = 1.f / (e0 + e1 + e2 + e3);
            out_c2[(size_t)r * 4 + 0] = e0 * inv;
            out_c2[(size_t)r * 4 + 1] = e1 * inv;
            out_c2[(size_t)r * 4 + 2] = e2 * inv;
            out_c2[(size_t)r * 4 + 3] = e3 * inv;
        }
    }
}

// ---------------------------------------------------------------------------
// launch
// ---------------------------------------------------------------------------
extern "C" void kernel_launch(void* const* d_in, const int* in_sizes, int n_in,
                              void* d_out, int out_size)
{
    // metadata order: x, W1, W2, W3, m1, m2, m3, wo1, bo1, wo2, bo2, wo3, bo3
    const float* x   = (const float*)d_in[0];
    const float* W1  = (const float*)d_in[1];
    const float* W2  = (const float*)d_in[2];
    const float* W3  = (const float*)d_in[3];
    const float* wo1 = (const float*)d_in[7];
    const float* bo1 = (const float*)d_in[8];
    const float* wo2 = (const float*)d_in[9];
    const float* bo2 = (const float*)d_in[10];
    const float* wo3 = (const float*)d_in[11];
    const float* bo3 = (const float*)d_in[12];

    float* out = (float*)d_out;
    // output layout: reg [B,10], c1 [B,3], c2 [B,4], feat [B,744]
    float* out_reg  = out;
    float* out_c1   = out + (size_t)BATCH * 10;
    float* out_c2   = out + (size_t)BATCH * 13;
    float* out_feat = out + (size_t)BATCH * 17;

    constexpr int B_TILE = 64;
    dim3 grid1((OUT_DIM + 255) / 256, BATCH / B_TILE);
    sparse_mlp_kernel<B_TILE><<<grid1, 256>>>(x, W1, W2, W3, out_feat);

    const int warps_needed = BATCH / 2;           // 2 rows per warp
    const int blocks2 = warps_needed / 8;         // 8 warps per block
    head_kernel<<<blocks2, 256>>>(out_feat, wo1, bo1, wo2, bo2, wo3, bo3,
                                  out_reg, out_c1, out_c2);
}